// round 15
// baseline (speedup 1.0000x reference)
#include <cuda_runtime.h>
#include <cuda_bf16.h>
#include <cstdint>

#define NNODES 50000
#define XROW   272      // IN_CH + POS_DIM
#define INC    256
#define HC     256      // HEADS * OUT_CH
#define NH     4
#define E0     500000
#define ET     550000   // edges + self loops

// ---- GEMM tiling ----
#define TILE_M 128
#define TILE_N 128
#define KCHUNK 64
#define SROW   144
#define SM_AHI 0
#define SM_ALO (SM_AHI + TILE_M * SROW)
#define SM_BHI (SM_ALO + TILE_M * SROW)
#define SM_BLO (SM_BHI + TILE_N * SROW)
#define SM_TOT (SM_BLO + TILE_N * SROW)   // 73728

#define SCANB 49    // 49 * 1024 >= 50000
#define WSPLITB 256 // blocks doing wsplit work in merged init kernel

// ---------------- scratch (static device globals; no allocation) ----------------
__device__ __align__(16) float          g_content[(size_t)NNODES * HC]; // 51.2 MB
__device__ __align__(16) __nv_bfloat16  g_whi[INC * HC];
__device__ __align__(16) __nv_bfloat16  g_wlo[INC * HC];
__device__ __align__(16) float    g_s[NNODES * NH];
__device__ __align__(16) float    g_dv[NNODES * NH];
__device__ __align__(16) float    g_denom[NNODES * NH];
__device__ __align__(16) float4   g_alpha[ET];          // exp(logit)
__device__ __align__(16) float4   g_salpha[ET];         // normalized, dest-sorted
__device__             int        g_scol[ET];           // col index, dest-sorted
__device__             int        g_count[NNODES];
__device__             int        g_rowptr[NNODES + 1];
__device__             int        g_cursor[NNODES];
__device__             int        g_psum[SCANB];
__device__             int        g_poff[SCANB];
__device__             float      g_S[16];

// ---------------- helpers ----------------
__device__ __forceinline__ void red_add_v4(float* p, float a, float b, float c, float d) {
    asm volatile("red.global.add.v4.f32 [%0], {%1,%2,%3,%4};"
                 :: "l"(p), "f"(a), "f"(b), "f"(c), "f"(d) : "memory");
}
__device__ __forceinline__ void red_add_f32(float* p, float a) {
    asm volatile("red.global.add.f32 [%0], %1;" :: "l"(p), "f"(a) : "memory");
}
__device__ __forceinline__ void split8(const float* f, uint4& hi, uint4& lo) {
    float r[8];
    __nv_bfloat162 h01 = __floats2bfloat162_rn(f[0], f[1]);
    __nv_bfloat162 h23 = __floats2bfloat162_rn(f[2], f[3]);
    __nv_bfloat162 h45 = __floats2bfloat162_rn(f[4], f[5]);
    __nv_bfloat162 h67 = __floats2bfloat162_rn(f[6], f[7]);
    r[0] = f[0] - __bfloat162float(h01.x); r[1] = f[1] - __bfloat162float(h01.y);
    r[2] = f[2] - __bfloat162float(h23.x); r[3] = f[3] - __bfloat162float(h23.y);
    r[4] = f[4] - __bfloat162float(h45.x); r[5] = f[5] - __bfloat162float(h45.y);
    r[6] = f[6] - __bfloat162float(h67.x); r[7] = f[7] - __bfloat162float(h67.y);
    __nv_bfloat162 l01 = __floats2bfloat162_rn(r[0], r[1]);
    __nv_bfloat162 l23 = __floats2bfloat162_rn(r[2], r[3]);
    __nv_bfloat162 l45 = __floats2bfloat162_rn(r[4], r[5]);
    __nv_bfloat162 l67 = __floats2bfloat162_rn(r[6], r[7]);
    hi.x = *(uint32_t*)&h01; hi.y = *(uint32_t*)&h23; hi.z = *(uint32_t*)&h45; hi.w = *(uint32_t*)&h67;
    lo.x = *(uint32_t*)&l01; lo.y = *(uint32_t*)&l23; lo.z = *(uint32_t*)&l45; lo.w = *(uint32_t*)&l67;
}
__device__ __forceinline__ void mma16816(float* d, const uint32_t* a, const uint32_t* b) {
    asm volatile(
        "mma.sync.aligned.m16n8k16.row.col.f32.bf16.bf16.f32 "
        "{%0,%1,%2,%3}, {%4,%5,%6,%7}, {%8,%9}, {%0,%1,%2,%3};"
        : "+f"(d[0]), "+f"(d[1]), "+f"(d[2]), "+f"(d[3])
        : "r"(a[0]), "r"(a[1]), "r"(a[2]), "r"(a[3]), "r"(b[0]), "r"(b[1]));
}

// ---------------- K0: merged init — W split (blocks 0..255) + pos logits (rest) ----------------
__global__ void __launch_bounds__(256) k_init(const float* __restrict__ x,
                                              const float* __restrict__ w,
                                              const float* __restrict__ patt) {
    if (blockIdx.x < WSPLITB) {
        const int i = blockIdx.x * 256 + threadIdx.x;
        if (i < INC * HC) {
            const float v = w[i];
            const __nv_bfloat16 h = __float2bfloat16_rn(v);
            g_whi[i] = h;
            g_wlo[i] = __float2bfloat16_rn(v - __bfloat162float(h));
        }
        return;
    }
    const int bid  = blockIdx.x - WSPLITB;
    const int gw   = (bid * 256 + threadIdx.x) >> 5;
    const int lane = threadIdx.x & 31;
    if (gw >= NNODES) return;
    const float pv = (lane < 16) ? x[(size_t)gw * XROW + INC + lane] : 0.f;
#pragma unroll
    for (int h = 0; h < NH; h++) {
        float vs = 0.f, vd = 0.f;
        if (lane < 16) {
            vs = pv * patt[h * 32 + lane];
            vd = pv * patt[h * 32 + 16 + lane];
        }
#pragma unroll
        for (int o = 8; o > 0; o >>= 1) {
            vs += __shfl_xor_sync(0xffffffffu, vs, o);
            vd += __shfl_xor_sync(0xffffffffu, vd, o);
        }
        if (lane == 0) { g_s[gw * NH + h] = vs; g_dv[gw * NH + h] = vd; }
    }
    if (lane < NH) g_denom[gw * NH + lane] = 0.f;
    if (lane == NH) g_count[gw] = 0;
}

// ---------------- K1: content = x @ W^T (HMMA split-bf16) + fused attention logits ----------------
__global__ void __launch_bounds__(256) k_gemm(const float* __restrict__ x,
                                              const float* __restrict__ att) {
    extern __shared__ char sm[];
    const int tid  = threadIdx.x;
    const int wid  = tid >> 5;
    const int lane = tid & 31;
    const int m0   = blockIdx.x * TILE_M;
    const int nb   = blockIdx.y * TILE_N;
    const int mo   = (wid >> 1) * 32;
    const int no   = (wid & 1) * 64;
    const int g    = lane >> 2;
    const int c    = lane & 3;

    float acc[2][8][4];
#pragma unroll
    for (int mi = 0; mi < 2; mi++)
#pragma unroll
        for (int ni = 0; ni < 8; ni++)
#pragma unroll
            for (int q = 0; q < 4; q++) acc[mi][ni][q] = 0.f;

    for (int ch = 0; ch < INC / KCHUNK; ch++) {
        const int k0 = ch * KCHUNK;
        {
            const int r = tid >> 1;
            const int h = (tid & 1) * 32;
            const int n = m0 + r;
            float f[32];
            if (n < NNODES) {
                const float4* p = reinterpret_cast<const float4*>(x + (size_t)n * XROW + k0 + h);
#pragma unroll
                for (int j = 0; j < 8; j++) {
                    float4 v = p[j];
                    f[j * 4 + 0] = v.x; f[j * 4 + 1] = v.y; f[j * 4 + 2] = v.z; f[j * 4 + 3] = v.w;
                }
            } else {
#pragma unroll
                for (int j = 0; j < 32; j++) f[j] = 0.f;
            }
#pragma unroll
            for (int g4 = 0; g4 < 4; g4++) {
                uint4 hi, lo;
                split8(f + g4 * 8, hi, lo);
                const int off = r * SROW + (h + g4 * 8) * 2;
                *reinterpret_cast<uint4*>(sm + SM_AHI + off) = hi;
                *reinterpret_cast<uint4*>(sm + SM_ALO + off) = lo;
            }
        }
        {
            const int r = tid >> 1;
            const int h = (tid & 1) * 32;
            const uint4* ph = reinterpret_cast<const uint4*>(g_whi + (size_t)(nb + r) * INC + k0 + h);
            const uint4* pl = reinterpret_cast<const uint4*>(g_wlo + (size_t)(nb + r) * INC + k0 + h);
            const int off = r * SROW + h * 2;
#pragma unroll
            for (int j = 0; j < 4; j++) {
                *reinterpret_cast<uint4*>(sm + SM_BHI + off + j * 16) = ph[j];
                *reinterpret_cast<uint4*>(sm + SM_BLO + off + j * 16) = pl[j];
            }
        }
        __syncthreads();

#pragma unroll
        for (int ks = 0; ks < 4; ks++) {
            const int kb = ks * 32 + c * 4;
            uint32_t ah[2][4], al[2][4];
#pragma unroll
            for (int mi = 0; mi < 2; mi++) {
                const int base = (mo + mi * 16 + g) * SROW + kb;
                ah[mi][0] = *reinterpret_cast<const uint32_t*>(sm + SM_AHI + base);
                ah[mi][1] = *reinterpret_cast<const uint32_t*>(sm + SM_AHI + base + 8 * SROW);
                ah[mi][2] = *reinterpret_cast<const uint32_t*>(sm + SM_AHI + base + 16);
                ah[mi][3] = *reinterpret_cast<const uint32_t*>(sm + SM_AHI + base + 8 * SROW + 16);
                al[mi][0] = *reinterpret_cast<const uint32_t*>(sm + SM_ALO + base);
                al[mi][1] = *reinterpret_cast<const uint32_t*>(sm + SM_ALO + base + 8 * SROW);
                al[mi][2] = *reinterpret_cast<const uint32_t*>(sm + SM_ALO + base + 16);
                al[mi][3] = *reinterpret_cast<const uint32_t*>(sm + SM_ALO + base + 8 * SROW + 16);
            }
#pragma unroll
            for (int ni = 0; ni < 8; ni++) {
                const int bbase = (no + ni * 8 + g) * SROW + kb;
                uint32_t bh[2], bl[2];
                bh[0] = *reinterpret_cast<const uint32_t*>(sm + SM_BHI + bbase);
                bh[1] = *reinterpret_cast<const uint32_t*>(sm + SM_BHI + bbase + 16);
                bl[0] = *reinterpret_cast<const uint32_t*>(sm + SM_BLO + bbase);
                bl[1] = *reinterpret_cast<const uint32_t*>(sm + SM_BLO + bbase + 16);
                mma16816(acc[0][ni], ah[0], bh);
                mma16816(acc[1][ni], ah[1], bh);
                mma16816(acc[0][ni], ah[0], bl);
                mma16816(acc[1][ni], ah[1], bl);
                mma16816(acc[0][ni], al[0], bh);
                mma16816(acc[1][ni], al[1], bh);
            }
        }
        __syncthreads();
    }

    // ---- epilogue 1: store content ----
#pragma unroll
    for (int mi = 0; mi < 2; mi++) {
        const int r0 = m0 + mo + mi * 16 + g;
        const int r1 = r0 + 8;
#pragma unroll
        for (int ni = 0; ni < 8; ni++) {
            const int col = nb + no + ni * 8 + c * 2;
            if (r0 < NNODES)
                *reinterpret_cast<float2*>(g_content + (size_t)r0 * HC + col) =
                    make_float2(acc[mi][ni][0], acc[mi][ni][1]);
            if (r1 < NNODES)
                *reinterpret_cast<float2*>(g_content + (size_t)r1 * HC + col) =
                    make_float2(acc[mi][ni][2], acc[mi][ni][3]);
        }
    }

    // ---- epilogue 2: fused attention logits (this warp owns full head h) ----
    const int h = (nb + no) >> 6;          // head index 0..3
    float as[16], ad[16];
#pragma unroll
    for (int ni = 0; ni < 8; ni++) {
#pragma unroll
        for (int q = 0; q < 2; q++) {
            const int ci = ni * 8 + c * 2 + q;
            as[ni * 2 + q] = att[h * 128 + ci];
            ad[ni * 2 + q] = att[h * 128 + 64 + ci];
        }
    }
#pragma unroll
    for (int mi = 0; mi < 2; mi++) {
        float vs0 = 0.f, vd0 = 0.f, vs1 = 0.f, vd1 = 0.f;
#pragma unroll
        for (int ni = 0; ni < 8; ni++) {
            vs0 = fmaf(acc[mi][ni][0], as[ni * 2], fmaf(acc[mi][ni][1], as[ni * 2 + 1], vs0));
            vd0 = fmaf(acc[mi][ni][0], ad[ni * 2], fmaf(acc[mi][ni][1], ad[ni * 2 + 1], vd0));
            vs1 = fmaf(acc[mi][ni][2], as[ni * 2], fmaf(acc[mi][ni][3], as[ni * 2 + 1], vs1));
            vd1 = fmaf(acc[mi][ni][2], ad[ni * 2], fmaf(acc[mi][ni][3], ad[ni * 2 + 1], vd1));
        }
#pragma unroll
        for (int o = 1; o <= 2; o <<= 1) {
            vs0 += __shfl_xor_sync(0xffffffffu, vs0, o);
            vd0 += __shfl_xor_sync(0xffffffffu, vd0, o);
            vs1 += __shfl_xor_sync(0xffffffffu, vs1, o);
            vd1 += __shfl_xor_sync(0xffffffffu, vd1, o);
        }
        if (c == 0) {
            const int r0 = m0 + mo + mi * 16 + g;
            const int r1 = r0 + 8;
            if (r0 < NNODES) {
                red_add_f32(g_s  + r0 * NH + h, vs0);
                red_add_f32(g_dv + r0 * NH + h, vd0);
            }
            if (r1 < NNODES) {
                red_add_f32(g_s  + r1 * NH + h, vs1);
                red_add_f32(g_dv + r1 * NH + h, vd1);
            }
        }
    }
}

// ---------------- K3: fused logits + leakyrelu + exp + denom + degree ----------------
__global__ void __launch_bounds__(256) k_logexp(const int* __restrict__ ei) {
    const int e = blockIdx.x * blockDim.x + threadIdx.x;
    if (e >= ET) return;
    int r, c;
    if (e < E0) { r = ei[e]; c = ei[E0 + e]; } else { r = c = e - E0; }
    const float4 sv = *reinterpret_cast<const float4*>(g_s  + r * NH);
    const float4 dv = *reinterpret_cast<const float4*>(g_dv + c * NH);
    float a0 = sv.x + dv.x, a1 = sv.y + dv.y, a2 = sv.z + dv.z, a3 = sv.w + dv.w;
    a0 = a0 > 0.f ? a0 : 0.2f * a0;
    a1 = a1 > 0.f ? a1 : 0.2f * a1;
    a2 = a2 > 0.f ? a2 : 0.2f * a2;
    a3 = a3 > 0.f ? a3 : 0.2f * a3;
    const float e0 = __expf(a0), e1 = __expf(a1), e2 = __expf(a2), e3 = __expf(a3);
    g_alpha[e] = make_float4(e0, e1, e2, e3);
    red_add_v4(g_denom + r * NH, e0, e1, e2, e3);
    atomicAdd(&g_count[r], 1);
}

// ---------------- K4a/b/c: coalesced 3-stage exclusive scan ----------------
__global__ void __launch_bounds__(1024) k_scan1() {
    __shared__ int sp[32];
    const int idx = blockIdx.x * 1024 + threadIdx.x;
    int v = (idx < NNODES) ? g_count[idx] : 0;
#pragma unroll
    for (int o = 16; o > 0; o >>= 1) v += __shfl_xor_sync(0xffffffffu, v, o);
    if ((threadIdx.x & 31) == 0) sp[threadIdx.x >> 5] = v;
    __syncthreads();
    if (threadIdx.x < 32) {
        int s = sp[threadIdx.x];
#pragma unroll
        for (int o = 16; o > 0; o >>= 1) s += __shfl_xor_sync(0xffffffffu, s, o);
        if (threadIdx.x == 0) g_psum[blockIdx.x] = s;
    }
}
__global__ void k_scan2() {
    const int t = threadIdx.x;   // 64 threads
    int v = (t < SCANB) ? g_psum[t] : 0;
    int acc = 0;
#pragma unroll
    for (int o = 1; o < 64; o <<= 1) {
        const int u = __shfl_up_sync(0xffffffffu, v, o, 32);
        if ((t & 31) >= o) v += u;
    }
    __shared__ int w0tot;
    if (t == 31) w0tot = v;
    __syncthreads();
    acc = (t >= 32) ? w0tot : 0;
    if (t < SCANB) g_poff[t] = v + acc - g_psum[t]; // exclusive
    if (t == 0) g_rowptr[NNODES] = ET;
    if (t < 16) g_S[t] = 0.f;
}
__global__ void __launch_bounds__(1024) k_scan3() {
    __shared__ int sw[32];
    const int idx = blockIdx.x * 1024 + threadIdx.x;
    const int lane = threadIdx.x & 31, wid = threadIdx.x >> 5;
    int v = (idx < NNODES) ? g_count[idx] : 0;
    const int mine = v;
#pragma unroll
    for (int o = 1; o < 32; o <<= 1) {
        const int u = __shfl_up_sync(0xffffffffu, v, o);
        if (lane >= o) v += u;
    }
    if (lane == 31) sw[wid] = v;
    __syncthreads();
    if (wid == 0) {
        int s = sw[lane];
#pragma unroll
        for (int o = 1; o < 32; o <<= 1) {
            const int u = __shfl_up_sync(0xffffffffu, s, o);
            if (lane >= o) s += u;
        }
        sw[lane] = s;
    }
    __syncthreads();
    const int warpoff = (wid > 0) ? sw[wid - 1] : 0;
    if (idx < NNODES) {
        const int excl = g_poff[blockIdx.x] + warpoff + v - mine;
        g_rowptr[idx] = excl;
        g_cursor[idx] = excl;
    }
}

// ---------------- K5: scatter edges dest-sorted + normalize + diversity sums ----------------
__global__ void __launch_bounds__(256) k_scatter(const int* __restrict__ ei) {
    __shared__ float red[8][10];
    const int e = blockIdx.x * 256 + threadIdx.x;
    float w0 = 0.f, w1 = 0.f, w2 = 0.f, w3 = 0.f;
    if (e < ET) {
        int r, c;
        if (e < E0) { r = ei[e]; c = ei[E0 + e]; } else { r = c = e - E0; }
        const float4 a   = g_alpha[e];
        const float4 den = *reinterpret_cast<const float4*>(g_denom + r * NH);
        w0 = a.x / (den.x + 1e-16f);
        w1 = a.y / (den.y + 1e-16f);
        w2 = a.z / (den.z + 1e-16f);
        w3 = a.w / (den.w + 1e-16f);
        const int pos = atomicAdd(&g_cursor[r], 1);
        g_scol[pos]   = c;
        g_salpha[pos] = make_float4(w0, w1, w2, w3);
    }
    float p[10];
    p[0] = w0 * w0; p[1] = w0 * w1; p[2] = w0 * w2; p[3] = w0 * w3;
    p[4] = w1 * w1; p[5] = w1 * w2; p[6] = w1 * w3;
    p[7] = w2 * w2; p[8] = w2 * w3; p[9] = w3 * w3;
#pragma unroll
    for (int i = 0; i < 10; i++)
#pragma unroll
        for (int o = 16; o > 0; o >>= 1)
            p[i] += __shfl_xor_sync(0xffffffffu, p[i], o);
    const int wid = threadIdx.x >> 5, lane = threadIdx.x & 31;
    if (lane == 0) {
#pragma unroll
        for (int i = 0; i < 10; i++) red[wid][i] = p[i];
    }
    __syncthreads();
    if (threadIdx.x < 10) {
        float s = 0.f;
#pragma unroll
        for (int k = 0; k < 8; k++) s += red[k][threadIdx.x];
        atomicAdd(&g_S[threadIdx.x], s);
    }
}

// ---------------- K6: CSR aggregation — 4 warps/node (1 head each), 16-edge batches ----------------
__global__ void __launch_bounds__(256) k_agg(float* __restrict__ out,
                                             const float* __restrict__ bias) {
    const int gw = (blockIdx.x * 256 + threadIdx.x) >> 5;
    const int n = gw >> 2;
    if (n >= NNODES) return;
    const int q    = gw & 3;                 // head
    const int lane = threadIdx.x & 31;
    const int beg = g_rowptr[n];
    const int end = g_rowptr[n + 1];
    const int coff = q * 32 + lane;          // float2 index within row (head q = float2 [q*32, q*32+32))
    const float* sal = reinterpret_cast<const float*>(g_salpha);

    float2 acc = make_float2(0.f, 0.f);
    for (int base = beg; base < end; base += 16) {
        // lanes 0-15 load cols, lanes 16-31 load weights for the same 16 edges
        const int slot = lane & 15;
        const int myj = base + slot;
        int   mycol = -1;
        float myw   = 0.f;
        if (myj < end) {
            if (lane < 16) mycol = g_scol[myj];
            else           myw   = sal[(size_t)myj * 4 + q];
        }
#pragma unroll
        for (int t = 0; t < 16; t++) {
            const int   c  = __shfl_sync(0xffffffffu, mycol, t);
            const float wv = __shfl_sync(0xffffffffu, myw, 16 + t);
            if (c >= 0) {
                const float2 v = reinterpret_cast<const float2*>(g_content + (size_t)c * HC)[coff];
                acc.x = fmaf(wv, v.x, acc.x);
                acc.y = fmaf(wv, v.y, acc.y);
            }
        }
    }
    const float2 b = reinterpret_cast<const float2*>(bias)[coff];
    reinterpret_cast<float2*>(out + (size_t)n * HC)[coff] =
        make_float2(acc.x + b.x, acc.y + b.y);
}

// ---------------- K7: diversity scalar ----------------
__global__ void k_finish(float* __restrict__ out, int outn) {
    if (blockIdx.x == 0 && threadIdx.x == 0) {
        const float n0 = fmaxf(sqrtf(g_S[0]), 1e-8f);
        const float n1 = fmaxf(sqrtf(g_S[4]), 1e-8f);
        const float n2 = fmaxf(sqrtf(g_S[7]), 1e-8f);
        const float n3 = fmaxf(sqrtf(g_S[9]), 1e-8f);
        float s = 0.f;
        s += 2.f * g_S[1] / (n0 * n1);
        s += 2.f * g_S[2] / (n0 * n2);
        s += 2.f * g_S[3] / (n0 * n3);
        s += 2.f * g_S[5] / (n1 * n2);
        s += 2.f * g_S[6] / (n1 * n3);
        s += 2.f * g_S[8] / (n2 * n3);
        out[outn] = (s / 16.f) * 0.1f;
    }
}

// ---------------- launch ----------------
extern "C" void kernel_launch(void* const* d_in, const int* in_sizes, int n_in,
                              void* d_out, int out_size) {
    const float* x    = (const float*)d_in[0];
    const int*   ei   = (const int*)d_in[1];
    const float* w    = (const float*)d_in[2];
    const float* att  = (const float*)d_in[3];
    const float* patt = (const float*)d_in[4];
    const float* bias = (const float*)d_in[5];
    float* out = (float*)d_out;
    const int outn = out_size - 1;

    static int smem_set = 0;
    if (!smem_set) {
        cudaFuncSetAttribute(k_gemm, cudaFuncAttributeMaxDynamicSharedMemorySize, SM_TOT);
        smem_set = 1;
    }

    dim3 ggrid((NNODES + TILE_M - 1) / TILE_M, HC / TILE_N);
    const int posblocks = (NNODES * 32 + 255) / 256;

    k_init   <<<WSPLITB + posblocks, 256>>>(x, w, patt);
    k_gemm   <<<ggrid, 256, SM_TOT>>>(x, att);
    k_logexp <<<(ET + 255) / 256, 256>>>(ei);
    k_scan1  <<<SCANB, 1024>>>();
    k_scan2  <<<1, 64>>>();
    k_scan3  <<<SCANB, 1024>>>();
    k_scatter<<<(ET + 255) / 256, 256>>>(ei);
    k_agg    <<<(NNODES * 4 * 32 + 255) / 256, 256>>>(out, bias);
    k_finish <<<1, 32>>>(out, outn);
}

// round 16
// speedup vs baseline: 1.1628x; 1.1628x over previous
#include <cuda_runtime.h>
#include <cuda_bf16.h>
#include <cuda_fp16.h>
#include <cstdint>

#define NNODES 50000
#define XROW   272      // IN_CH + POS_DIM
#define INC    256
#define HC     256      // HEADS * OUT_CH
#define NH     4
#define E0     500000
#define ET     550000   // edges + self loops

// ---- GEMM tiling ----
#define TILE_M 128
#define TILE_N 128
#define KCHUNK 64
#define SROW   144
#define SM_AHI 0
#define SM_ALO (SM_AHI + TILE_M * SROW)
#define SM_BHI (SM_ALO + TILE_M * SROW)
#define SM_BLO (SM_BHI + TILE_N * SROW)
#define SM_TOT (SM_BLO + TILE_N * SROW)   // 73728

#define SCANB 49    // 49 * 1024 >= 50000
#define WSPLITB 256 // blocks doing wsplit work in merged init kernel

// ---------------- scratch (static device globals; no allocation) ----------------
__device__ __align__(16) __half         g_contenth[(size_t)NNODES * HC]; // 25.6 MB fp16
__device__ __align__(16) __nv_bfloat16  g_whi[INC * HC];
__device__ __align__(16) __nv_bfloat16  g_wlo[INC * HC];
__device__ __align__(16) float    g_s[NNODES * NH];
__device__ __align__(16) float    g_dv[NNODES * NH];
__device__ __align__(16) float    g_denom[NNODES * NH];
__device__ __align__(16) float4   g_alpha[ET];          // exp(logit)
__device__ __align__(16) float4   g_salpha[ET];         // normalized, dest-sorted
__device__             int        g_scol[ET];           // col index, dest-sorted
__device__             int        g_count[NNODES];
__device__             int        g_rowptr[NNODES + 1];
__device__             int        g_cursor[NNODES];
__device__             int        g_psum[SCANB];
__device__             int        g_poff[SCANB];
__device__             float      g_S[16];

// ---------------- helpers ----------------
__device__ __forceinline__ void red_add_v4(float* p, float a, float b, float c, float d) {
    asm volatile("red.global.add.v4.f32 [%0], {%1,%2,%3,%4};"
                 :: "l"(p), "f"(a), "f"(b), "f"(c), "f"(d) : "memory");
}
__device__ __forceinline__ void red_add_f32(float* p, float a) {
    asm volatile("red.global.add.f32 [%0], %1;" :: "l"(p), "f"(a) : "memory");
}
__device__ __forceinline__ void split8(const float* f, uint4& hi, uint4& lo) {
    float r[8];
    __nv_bfloat162 h01 = __floats2bfloat162_rn(f[0], f[1]);
    __nv_bfloat162 h23 = __floats2bfloat162_rn(f[2], f[3]);
    __nv_bfloat162 h45 = __floats2bfloat162_rn(f[4], f[5]);
    __nv_bfloat162 h67 = __floats2bfloat162_rn(f[6], f[7]);
    r[0] = f[0] - __bfloat162float(h01.x); r[1] = f[1] - __bfloat162float(h01.y);
    r[2] = f[2] - __bfloat162float(h23.x); r[3] = f[3] - __bfloat162float(h23.y);
    r[4] = f[4] - __bfloat162float(h45.x); r[5] = f[5] - __bfloat162float(h45.y);
    r[6] = f[6] - __bfloat162float(h67.x); r[7] = f[7] - __bfloat162float(h67.y);
    __nv_bfloat162 l01 = __floats2bfloat162_rn(r[0], r[1]);
    __nv_bfloat162 l23 = __floats2bfloat162_rn(r[2], r[3]);
    __nv_bfloat162 l45 = __floats2bfloat162_rn(r[4], r[5]);
    __nv_bfloat162 l67 = __floats2bfloat162_rn(r[6], r[7]);
    hi.x = *(uint32_t*)&h01; hi.y = *(uint32_t*)&h23; hi.z = *(uint32_t*)&h45; hi.w = *(uint32_t*)&h67;
    lo.x = *(uint32_t*)&l01; lo.y = *(uint32_t*)&l23; lo.z = *(uint32_t*)&l45; lo.w = *(uint32_t*)&l67;
}
__device__ __forceinline__ void mma16816(float* d, const uint32_t* a, const uint32_t* b) {
    asm volatile(
        "mma.sync.aligned.m16n8k16.row.col.f32.bf16.bf16.f32 "
        "{%0,%1,%2,%3}, {%4,%5,%6,%7}, {%8,%9}, {%0,%1,%2,%3};"
        : "+f"(d[0]), "+f"(d[1]), "+f"(d[2]), "+f"(d[3])
        : "r"(a[0]), "r"(a[1]), "r"(a[2]), "r"(a[3]), "r"(b[0]), "r"(b[1]));
}

// ---------------- K0: merged init — W split (blocks 0..255) + pos logits (rest) ----------------
__global__ void __launch_bounds__(256) k_init(const float* __restrict__ x,
                                              const float* __restrict__ w,
                                              const float* __restrict__ patt) {
    if (blockIdx.x < WSPLITB) {
        const int i = blockIdx.x * 256 + threadIdx.x;
        if (i < INC * HC) {
            const float v = w[i];
            const __nv_bfloat16 h = __float2bfloat16_rn(v);
            g_whi[i] = h;
            g_wlo[i] = __float2bfloat16_rn(v - __bfloat162float(h));
        }
        return;
    }
    const int bid  = blockIdx.x - WSPLITB;
    const int gw   = (bid * 256 + threadIdx.x) >> 5;
    const int lane = threadIdx.x & 31;
    if (gw >= NNODES) return;
    const float pv = (lane < 16) ? x[(size_t)gw * XROW + INC + lane] : 0.f;
#pragma unroll
    for (int h = 0; h < NH; h++) {
        float vs = 0.f, vd = 0.f;
        if (lane < 16) {
            vs = pv * patt[h * 32 + lane];
            vd = pv * patt[h * 32 + 16 + lane];
        }
#pragma unroll
        for (int o = 8; o > 0; o >>= 1) {
            vs += __shfl_xor_sync(0xffffffffu, vs, o);
            vd += __shfl_xor_sync(0xffffffffu, vd, o);
        }
        if (lane == 0) { g_s[gw * NH + h] = vs; g_dv[gw * NH + h] = vd; }
    }
    if (lane < NH) g_denom[gw * NH + lane] = 0.f;
    if (lane == NH) g_count[gw] = 0;
}

// ---------------- K1: content = x @ W^T (HMMA split-bf16) + fused attention logits ----------------
__global__ void __launch_bounds__(256) k_gemm(const float* __restrict__ x,
                                              const float* __restrict__ att) {
    extern __shared__ char sm[];
    const int tid  = threadIdx.x;
    const int wid  = tid >> 5;
    const int lane = tid & 31;
    const int m0   = blockIdx.x * TILE_M;
    const int nb   = blockIdx.y * TILE_N;
    const int mo   = (wid >> 1) * 32;
    const int no   = (wid & 1) * 64;
    const int g    = lane >> 2;
    const int c    = lane & 3;

    float acc[2][8][4];
#pragma unroll
    for (int mi = 0; mi < 2; mi++)
#pragma unroll
        for (int ni = 0; ni < 8; ni++)
#pragma unroll
            for (int q = 0; q < 4; q++) acc[mi][ni][q] = 0.f;

    for (int ch = 0; ch < INC / KCHUNK; ch++) {
        const int k0 = ch * KCHUNK;
        {
            const int r = tid >> 1;
            const int h = (tid & 1) * 32;
            const int n = m0 + r;
            float f[32];
            if (n < NNODES) {
                const float4* p = reinterpret_cast<const float4*>(x + (size_t)n * XROW + k0 + h);
#pragma unroll
                for (int j = 0; j < 8; j++) {
                    float4 v = p[j];
                    f[j * 4 + 0] = v.x; f[j * 4 + 1] = v.y; f[j * 4 + 2] = v.z; f[j * 4 + 3] = v.w;
                }
            } else {
#pragma unroll
                for (int j = 0; j < 32; j++) f[j] = 0.f;
            }
#pragma unroll
            for (int g4 = 0; g4 < 4; g4++) {
                uint4 hi, lo;
                split8(f + g4 * 8, hi, lo);
                const int off = r * SROW + (h + g4 * 8) * 2;
                *reinterpret_cast<uint4*>(sm + SM_AHI + off) = hi;
                *reinterpret_cast<uint4*>(sm + SM_ALO + off) = lo;
            }
        }
        {
            const int r = tid >> 1;
            const int h = (tid & 1) * 32;
            const uint4* ph = reinterpret_cast<const uint4*>(g_whi + (size_t)(nb + r) * INC + k0 + h);
            const uint4* pl = reinterpret_cast<const uint4*>(g_wlo + (size_t)(nb + r) * INC + k0 + h);
            const int off = r * SROW + h * 2;
#pragma unroll
            for (int j = 0; j < 4; j++) {
                *reinterpret_cast<uint4*>(sm + SM_BHI + off + j * 16) = ph[j];
                *reinterpret_cast<uint4*>(sm + SM_BLO + off + j * 16) = pl[j];
            }
        }
        __syncthreads();

#pragma unroll
        for (int ks = 0; ks < 4; ks++) {
            const int kb = ks * 32 + c * 4;
            uint32_t ah[2][4], al[2][4];
#pragma unroll
            for (int mi = 0; mi < 2; mi++) {
                const int base = (mo + mi * 16 + g) * SROW + kb;
                ah[mi][0] = *reinterpret_cast<const uint32_t*>(sm + SM_AHI + base);
                ah[mi][1] = *reinterpret_cast<const uint32_t*>(sm + SM_AHI + base + 8 * SROW);
                ah[mi][2] = *reinterpret_cast<const uint32_t*>(sm + SM_AHI + base + 16);
                ah[mi][3] = *reinterpret_cast<const uint32_t*>(sm + SM_AHI + base + 8 * SROW + 16);
                al[mi][0] = *reinterpret_cast<const uint32_t*>(sm + SM_ALO + base);
                al[mi][1] = *reinterpret_cast<const uint32_t*>(sm + SM_ALO + base + 8 * SROW);
                al[mi][2] = *reinterpret_cast<const uint32_t*>(sm + SM_ALO + base + 16);
                al[mi][3] = *reinterpret_cast<const uint32_t*>(sm + SM_ALO + base + 8 * SROW + 16);
            }
#pragma unroll
            for (int ni = 0; ni < 8; ni++) {
                const int bbase = (no + ni * 8 + g) * SROW + kb;
                uint32_t bh[2], bl[2];
                bh[0] = *reinterpret_cast<const uint32_t*>(sm + SM_BHI + bbase);
                bh[1] = *reinterpret_cast<const uint32_t*>(sm + SM_BHI + bbase + 16);
                bl[0] = *reinterpret_cast<const uint32_t*>(sm + SM_BLO + bbase);
                bl[1] = *reinterpret_cast<const uint32_t*>(sm + SM_BLO + bbase + 16);
                mma16816(acc[0][ni], ah[0], bh);
                mma16816(acc[1][ni], ah[1], bh);
                mma16816(acc[0][ni], ah[0], bl);
                mma16816(acc[1][ni], ah[1], bl);
                mma16816(acc[0][ni], al[0], bh);
                mma16816(acc[1][ni], al[1], bh);
            }
        }
        __syncthreads();
    }

    // ---- epilogue 1: store content as fp16 ----
#pragma unroll
    for (int mi = 0; mi < 2; mi++) {
        const int r0 = m0 + mo + mi * 16 + g;
        const int r1 = r0 + 8;
#pragma unroll
        for (int ni = 0; ni < 8; ni++) {
            const int col = nb + no + ni * 8 + c * 2;
            if (r0 < NNODES) {
                const __half2 h2 = __floats2half2_rn(acc[mi][ni][0], acc[mi][ni][1]);
                *reinterpret_cast<uint32_t*>(
                    reinterpret_cast<char*>(g_contenth) + ((size_t)r0 * HC + col) * 2) =
                    *reinterpret_cast<const uint32_t*>(&h2);
            }
            if (r1 < NNODES) {
                const __half2 h2 = __floats2half2_rn(acc[mi][ni][2], acc[mi][ni][3]);
                *reinterpret_cast<uint32_t*>(
                    reinterpret_cast<char*>(g_contenth) + ((size_t)r1 * HC + col) * 2) =
                    *reinterpret_cast<const uint32_t*>(&h2);
            }
        }
    }

    // ---- epilogue 2: fused attention logits (this warp owns full head h) ----
    const int h = (nb + no) >> 6;          // head index 0..3
    float as[16], ad[16];
#pragma unroll
    for (int ni = 0; ni < 8; ni++) {
#pragma unroll
        for (int q = 0; q < 2; q++) {
            const int ci = ni * 8 + c * 2 + q;
            as[ni * 2 + q] = att[h * 128 + ci];
            ad[ni * 2 + q] = att[h * 128 + 64 + ci];
        }
    }
#pragma unroll
    for (int mi = 0; mi < 2; mi++) {
        float vs0 = 0.f, vd0 = 0.f, vs1 = 0.f, vd1 = 0.f;
#pragma unroll
        for (int ni = 0; ni < 8; ni++) {
            vs0 = fmaf(acc[mi][ni][0], as[ni * 2], fmaf(acc[mi][ni][1], as[ni * 2 + 1], vs0));
            vd0 = fmaf(acc[mi][ni][0], ad[ni * 2], fmaf(acc[mi][ni][1], ad[ni * 2 + 1], vd0));
            vs1 = fmaf(acc[mi][ni][2], as[ni * 2], fmaf(acc[mi][ni][3], as[ni * 2 + 1], vs1));
            vd1 = fmaf(acc[mi][ni][2], ad[ni * 2], fmaf(acc[mi][ni][3], ad[ni * 2 + 1], vd1));
        }
#pragma unroll
        for (int o = 1; o <= 2; o <<= 1) {
            vs0 += __shfl_xor_sync(0xffffffffu, vs0, o);
            vd0 += __shfl_xor_sync(0xffffffffu, vd0, o);
            vs1 += __shfl_xor_sync(0xffffffffu, vs1, o);
            vd1 += __shfl_xor_sync(0xffffffffu, vd1, o);
        }
        if (c == 0) {
            const int r0 = m0 + mo + mi * 16 + g;
            const int r1 = r0 + 8;
            if (r0 < NNODES) {
                red_add_f32(g_s  + r0 * NH + h, vs0);
                red_add_f32(g_dv + r0 * NH + h, vd0);
            }
            if (r1 < NNODES) {
                red_add_f32(g_s  + r1 * NH + h, vs1);
                red_add_f32(g_dv + r1 * NH + h, vd1);
            }
        }
    }
}

// ---------------- K3: fused logits + leakyrelu + exp + denom + degree ----------------
__global__ void __launch_bounds__(256) k_logexp(const int* __restrict__ ei) {
    const int e = blockIdx.x * blockDim.x + threadIdx.x;
    if (e >= ET) return;
    int r, c;
    if (e < E0) { r = ei[e]; c = ei[E0 + e]; } else { r = c = e - E0; }
    const float4 sv = *reinterpret_cast<const float4*>(g_s  + r * NH);
    const float4 dv = *reinterpret_cast<const float4*>(g_dv + c * NH);
    float a0 = sv.x + dv.x, a1 = sv.y + dv.y, a2 = sv.z + dv.z, a3 = sv.w + dv.w;
    a0 = a0 > 0.f ? a0 : 0.2f * a0;
    a1 = a1 > 0.f ? a1 : 0.2f * a1;
    a2 = a2 > 0.f ? a2 : 0.2f * a2;
    a3 = a3 > 0.f ? a3 : 0.2f * a3;
    const float e0 = __expf(a0), e1 = __expf(a1), e2 = __expf(a2), e3 = __expf(a3);
    g_alpha[e] = make_float4(e0, e1, e2, e3);
    red_add_v4(g_denom + r * NH, e0, e1, e2, e3);
    atomicAdd(&g_count[r], 1);
}

// ---------------- K4a/b/c: coalesced 3-stage exclusive scan ----------------
__global__ void __launch_bounds__(1024) k_scan1() {
    __shared__ int sp[32];
    const int idx = blockIdx.x * 1024 + threadIdx.x;
    int v = (idx < NNODES) ? g_count[idx] : 0;
#pragma unroll
    for (int o = 16; o > 0; o >>= 1) v += __shfl_xor_sync(0xffffffffu, v, o);
    if ((threadIdx.x & 31) == 0) sp[threadIdx.x >> 5] = v;
    __syncthreads();
    if (threadIdx.x < 32) {
        int s = sp[threadIdx.x];
#pragma unroll
        for (int o = 16; o > 0; o >>= 1) s += __shfl_xor_sync(0xffffffffu, s, o);
        if (threadIdx.x == 0) g_psum[blockIdx.x] = s;
    }
}
__global__ void k_scan2() {
    const int t = threadIdx.x;   // 64 threads
    int v = (t < SCANB) ? g_psum[t] : 0;
    int acc = 0;
#pragma unroll
    for (int o = 1; o < 64; o <<= 1) {
        const int u = __shfl_up_sync(0xffffffffu, v, o, 32);
        if ((t & 31) >= o) v += u;
    }
    __shared__ int w0tot;
    if (t == 31) w0tot = v;
    __syncthreads();
    acc = (t >= 32) ? w0tot : 0;
    if (t < SCANB) g_poff[t] = v + acc - g_psum[t]; // exclusive
    if (t == 0) g_rowptr[NNODES] = ET;
    if (t < 16) g_S[t] = 0.f;
}
__global__ void __launch_bounds__(1024) k_scan3() {
    __shared__ int sw[32];
    const int idx = blockIdx.x * 1024 + threadIdx.x;
    const int lane = threadIdx.x & 31, wid = threadIdx.x >> 5;
    int v = (idx < NNODES) ? g_count[idx] : 0;
    const int mine = v;
#pragma unroll
    for (int o = 1; o < 32; o <<= 1) {
        const int u = __shfl_up_sync(0xffffffffu, v, o);
        if (lane >= o) v += u;
    }
    if (lane == 31) sw[wid] = v;
    __syncthreads();
    if (wid == 0) {
        int s = sw[lane];
#pragma unroll
        for (int o = 1; o < 32; o <<= 1) {
            const int u = __shfl_up_sync(0xffffffffu, s, o);
            if (lane >= o) s += u;
        }
        sw[lane] = s;
    }
    __syncthreads();
    const int warpoff = (wid > 0) ? sw[wid - 1] : 0;
    if (idx < NNODES) {
        const int excl = g_poff[blockIdx.x] + warpoff + v - mine;
        g_rowptr[idx] = excl;
        g_cursor[idx] = excl;
    }
}

// ---------------- K5: scatter edges dest-sorted + normalize + diversity sums ----------------
__global__ void __launch_bounds__(256) k_scatter(const int* __restrict__ ei) {
    __shared__ float red[8][10];
    const int e = blockIdx.x * 256 + threadIdx.x;
    float w0 = 0.f, w1 = 0.f, w2 = 0.f, w3 = 0.f;
    if (e < ET) {
        int r, c;
        if (e < E0) { r = ei[e]; c = ei[E0 + e]; } else { r = c = e - E0; }
        const float4 a   = g_alpha[e];
        const float4 den = *reinterpret_cast<const float4*>(g_denom + r * NH);
        w0 = a.x / (den.x + 1e-16f);
        w1 = a.y / (den.y + 1e-16f);
        w2 = a.z / (den.z + 1e-16f);
        w3 = a.w / (den.w + 1e-16f);
        const int pos = atomicAdd(&g_cursor[r], 1);
        g_scol[pos]   = c;
        g_salpha[pos] = make_float4(w0, w1, w2, w3);
    }
    float p[10];
    p[0] = w0 * w0; p[1] = w0 * w1; p[2] = w0 * w2; p[3] = w0 * w3;
    p[4] = w1 * w1; p[5] = w1 * w2; p[6] = w1 * w3;
    p[7] = w2 * w2; p[8] = w2 * w3; p[9] = w3 * w3;
#pragma unroll
    for (int i = 0; i < 10; i++)
#pragma unroll
        for (int o = 16; o > 0; o >>= 1)
            p[i] += __shfl_xor_sync(0xffffffffu, p[i], o);
    const int wid = threadIdx.x >> 5, lane = threadIdx.x & 31;
    if (lane == 0) {
#pragma unroll
        for (int i = 0; i < 10; i++) red[wid][i] = p[i];
    }
    __syncthreads();
    if (threadIdx.x < 10) {
        float s = 0.f;
#pragma unroll
        for (int k = 0; k < 8; k++) s += red[k][threadIdx.x];
        atomicAdd(&g_S[threadIdx.x], s);
    }
}

// ---------------- K6: CSR aggregation — 2 warps/node, fp16 content, 16-edge batches ----------------
__global__ void __launch_bounds__(256) k_agg(float* __restrict__ out,
                                             const float* __restrict__ bias) {
    const int gw = (blockIdx.x * 256 + threadIdx.x) >> 5;
    const int n = gw >> 1;
    if (n >= NNODES) return;
    const int hf   = gw & 1;
    const int lane = threadIdx.x & 31;
    const int beg = g_rowptr[n];
    const int end = g_rowptr[n + 1];
    const int coff = hf * 32 + lane;         // 4-channel group index (channels coff*4..+3)
    const float* sal = reinterpret_cast<const float*>(g_salpha);

    float4 acc = make_float4(0.f, 0.f, 0.f, 0.f);
    for (int base = beg; base < end; base += 16) {
        const int slot = lane & 15;
        const int myj = base + slot;
        int   mycol = -1;
        float mywx = 0.f, mywy = 0.f;
        if (myj < end) {
            if (lane < 16) {
                mycol = g_scol[myj];
            } else {
                const float2 w2 = *reinterpret_cast<const float2*>(sal + (size_t)myj * 4 + hf * 2);
                mywx = w2.x; mywy = w2.y;
            }
        }
#pragma unroll
        for (int t = 0; t < 16; t++) {
            const int   c  = __shfl_sync(0xffffffffu, mycol, t);
            const float wx = __shfl_sync(0xffffffffu, mywx, 16 + t);
            const float wy = __shfl_sync(0xffffffffu, mywy, 16 + t);
            if (c >= 0) {
                const float wv = (lane < 16) ? wx : wy;
                const uint2 raw = reinterpret_cast<const uint2*>(
                    reinterpret_cast<const char*>(g_contenth) + (size_t)c * HC * 2)[coff];
                const __half2 h0 = *reinterpret_cast<const __half2*>(&raw.x);
                const __half2 h1 = *reinterpret_cast<const __half2*>(&raw.y);
                const float2 f0 = __half22float2(h0);
                const float2 f1 = __half22float2(h1);
                acc.x = fmaf(wv, f0.x, acc.x);
                acc.y = fmaf(wv, f0.y, acc.y);
                acc.z = fmaf(wv, f1.x, acc.z);
                acc.w = fmaf(wv, f1.y, acc.w);
            }
        }
    }
    const float4 b = reinterpret_cast<const float4*>(bias)[coff];
    reinterpret_cast<float4*>(out + (size_t)n * HC)[coff] =
        make_float4(acc.x + b.x, acc.y + b.y, acc.z + b.z, acc.w + b.w);
}

// ---------------- K7: diversity scalar ----------------
__global__ void k_finish(float* __restrict__ out, int outn) {
    if (blockIdx.x == 0 && threadIdx.x == 0) {
        const float n0 = fmaxf(sqrtf(g_S[0]), 1e-8f);
        const float n1 = fmaxf(sqrtf(g_S[4]), 1e-8f);
        const float n2 = fmaxf(sqrtf(g_S[7]), 1e-8f);
        const float n3 = fmaxf(sqrtf(g_S[9]), 1e-8f);
        float s = 0.f;
        s += 2.f * g_S[1] / (n0 * n1);
        s += 2.f * g_S[2] / (n0 * n2);
        s += 2.f * g_S[3] / (n0 * n3);
        s += 2.f * g_S[5] / (n1 * n2);
        s += 2.f * g_S[6] / (n1 * n3);
        s += 2.f * g_S[8] / (n2 * n3);
        out[outn] = (s / 16.f) * 0.1f;
    }
}

// ---------------- launch ----------------
extern "C" void kernel_launch(void* const* d_in, const int* in_sizes, int n_in,
                              void* d_out, int out_size) {
    const float* x    = (const float*)d_in[0];
    const int*   ei   = (const int*)d_in[1];
    const float* w    = (const float*)d_in[2];
    const float* att  = (const float*)d_in[3];
    const float* patt = (const float*)d_in[4];
    const float* bias = (const float*)d_in[5];
    float* out = (float*)d_out;
    const int outn = out_size - 1;

    static int smem_set = 0;
    if (!smem_set) {
        cudaFuncSetAttribute(k_gemm, cudaFuncAttributeMaxDynamicSharedMemorySize, SM_TOT);
        smem_set = 1;
    }

    dim3 ggrid((NNODES + TILE_M - 1) / TILE_M, HC / TILE_N);
    const int posblocks = (NNODES * 32 + 255) / 256;

    k_init   <<<WSPLITB + posblocks, 256>>>(x, w, patt);
    k_gemm   <<<ggrid, 256, SM_TOT>>>(x, att);
    k_logexp <<<(ET + 255) / 256, 256>>>(ei);
    k_scan1  <<<SCANB, 1024>>>();
    k_scan2  <<<1, 64>>>();
    k_scan3  <<<SCANB, 1024>>>();
    k_scatter<<<(ET + 255) / 256, 256>>>(ei);
    k_agg    <<<(NNODES * 2 * 32 + 255) / 256, 256>>>(out, bias);
    k_finish <<<1, 32>>>(out, outn);
}

// round 17
// speedup vs baseline: 1.1763x; 1.0116x over previous
#include <cuda_runtime.h>
#include <cuda_bf16.h>
#include <cuda_fp16.h>
#include <cstdint>

#define NNODES 50000
#define XROW   272      // IN_CH + POS_DIM
#define INC    256
#define HC     256      // HEADS * OUT_CH
#define NH     4
#define E0     500000
#define ET     550000   // edges + self loops

// ---- GEMM tiling ----
#define TILE_M 128
#define TILE_N 128
#define KCHUNK 64
#define SROW   144
#define SM_AHI 0
#define SM_ALO (SM_AHI + TILE_M * SROW)
#define SM_BHI (SM_ALO + TILE_M * SROW)
#define SM_BLO (SM_BHI + TILE_N * SROW)
#define SM_TOT (SM_BLO + TILE_N * SROW)   // 73728

#define SCANB 49    // 49 * 1024 >= 50000
#define WSPLITB 256 // blocks doing wsplit work in merged init kernel

// ---------------- scratch (static device globals; no allocation) ----------------
__device__ __align__(16) __half         g_contenth[(size_t)NNODES * HC]; // 25.6 MB fp16
__device__ __align__(16) __nv_bfloat16  g_whi[INC * HC];
__device__ __align__(16) __nv_bfloat16  g_wlo[INC * HC];
__device__ __align__(16) float    g_s[NNODES * NH];
__device__ __align__(16) float    g_dv[NNODES * NH];
__device__ __align__(16) float    g_denom[NNODES * NH];
__device__ __align__(16) float4   g_alpha[ET];          // exp(logit)
__device__ __align__(16) float4   g_salpha[ET];         // normalized, dest-sorted
__device__             int        g_scol[ET];           // col index, dest-sorted
__device__             int        g_count[NNODES];
__device__             int        g_rowptr[NNODES + 1];
__device__             int        g_cursor[NNODES];
__device__             int        g_psum[SCANB];
__device__             int        g_poff[SCANB];
__device__             float      g_S[16];

// ---------------- helpers ----------------
__device__ __forceinline__ void red_add_v4(float* p, float a, float b, float c, float d) {
    asm volatile("red.global.add.v4.f32 [%0], {%1,%2,%3,%4};"
                 :: "l"(p), "f"(a), "f"(b), "f"(c), "f"(d) : "memory");
}
__device__ __forceinline__ void red_add_f32(float* p, float a) {
    asm volatile("red.global.add.f32 [%0], %1;" :: "l"(p), "f"(a) : "memory");
}
__device__ __forceinline__ void split8(const float* f, uint4& hi, uint4& lo) {
    float r[8];
    __nv_bfloat162 h01 = __floats2bfloat162_rn(f[0], f[1]);
    __nv_bfloat162 h23 = __floats2bfloat162_rn(f[2], f[3]);
    __nv_bfloat162 h45 = __floats2bfloat162_rn(f[4], f[5]);
    __nv_bfloat162 h67 = __floats2bfloat162_rn(f[6], f[7]);
    r[0] = f[0] - __bfloat162float(h01.x); r[1] = f[1] - __bfloat162float(h01.y);
    r[2] = f[2] - __bfloat162float(h23.x); r[3] = f[3] - __bfloat162float(h23.y);
    r[4] = f[4] - __bfloat162float(h45.x); r[5] = f[5] - __bfloat162float(h45.y);
    r[6] = f[6] - __bfloat162float(h67.x); r[7] = f[7] - __bfloat162float(h67.y);
    __nv_bfloat162 l01 = __floats2bfloat162_rn(r[0], r[1]);
    __nv_bfloat162 l23 = __floats2bfloat162_rn(r[2], r[3]);
    __nv_bfloat162 l45 = __floats2bfloat162_rn(r[4], r[5]);
    __nv_bfloat162 l67 = __floats2bfloat162_rn(r[6], r[7]);
    hi.x = *(uint32_t*)&h01; hi.y = *(uint32_t*)&h23; hi.z = *(uint32_t*)&h45; hi.w = *(uint32_t*)&h67;
    lo.x = *(uint32_t*)&l01; lo.y = *(uint32_t*)&l23; lo.z = *(uint32_t*)&l45; lo.w = *(uint32_t*)&l67;
}
__device__ __forceinline__ void mma16816(float* d, const uint32_t* a, const uint32_t* b) {
    asm volatile(
        "mma.sync.aligned.m16n8k16.row.col.f32.bf16.bf16.f32 "
        "{%0,%1,%2,%3}, {%4,%5,%6,%7}, {%8,%9}, {%0,%1,%2,%3};"
        : "+f"(d[0]), "+f"(d[1]), "+f"(d[2]), "+f"(d[3])
        : "r"(a[0]), "r"(a[1]), "r"(a[2]), "r"(a[3]), "r"(b[0]), "r"(b[1]));
}

// ---------------- K0: merged init — W split (blocks 0..255) + pos logits (rest) ----------------
__global__ void __launch_bounds__(256) k_init(const float* __restrict__ x,
                                              const float* __restrict__ w,
                                              const float* __restrict__ patt) {
    if (blockIdx.x < WSPLITB) {
        const int i = blockIdx.x * 256 + threadIdx.x;
        if (i < INC * HC) {
            const float v = w[i];
            const __nv_bfloat16 h = __float2bfloat16_rn(v);
            g_whi[i] = h;
            g_wlo[i] = __float2bfloat16_rn(v - __bfloat162float(h));
        }
        return;
    }
    const int bid  = blockIdx.x - WSPLITB;
    const int gw   = (bid * 256 + threadIdx.x) >> 5;
    const int lane = threadIdx.x & 31;
    if (gw >= NNODES) return;
    const float pv = (lane < 16) ? x[(size_t)gw * XROW + INC + lane] : 0.f;
#pragma unroll
    for (int h = 0; h < NH; h++) {
        float vs = 0.f, vd = 0.f;
        if (lane < 16) {
            vs = pv * patt[h * 32 + lane];
            vd = pv * patt[h * 32 + 16 + lane];
        }
#pragma unroll
        for (int o = 8; o > 0; o >>= 1) {
            vs += __shfl_xor_sync(0xffffffffu, vs, o);
            vd += __shfl_xor_sync(0xffffffffu, vd, o);
        }
        if (lane == 0) { g_s[gw * NH + h] = vs; g_dv[gw * NH + h] = vd; }
    }
    if (lane < NH) g_denom[gw * NH + lane] = 0.f;
}

// ---------------- side stream: degree histogram ----------------
__global__ void k_zero_count() {
    const int i = blockIdx.x * 256 + threadIdx.x;
    if (i < NNODES) g_count[i] = 0;
}
__global__ void __launch_bounds__(256) k_count(const int* __restrict__ ei) {
    const int e = blockIdx.x * 256 + threadIdx.x;
    if (e >= ET) return;
    const int r = (e < E0) ? ei[e] : e - E0;
    atomicAdd(&g_count[r], 1);
}

// ---------------- K1: content = x @ W^T (HMMA split-bf16) + fused attention logits ----------------
__global__ void __launch_bounds__(256) k_gemm(const float* __restrict__ x,
                                              const float* __restrict__ att) {
    extern __shared__ char sm[];
    const int tid  = threadIdx.x;
    const int wid  = tid >> 5;
    const int lane = tid & 31;
    const int m0   = blockIdx.x * TILE_M;
    const int nb   = blockIdx.y * TILE_N;
    const int mo   = (wid >> 1) * 32;
    const int no   = (wid & 1) * 64;
    const int g    = lane >> 2;
    const int c    = lane & 3;

    float acc[2][8][4];
#pragma unroll
    for (int mi = 0; mi < 2; mi++)
#pragma unroll
        for (int ni = 0; ni < 8; ni++)
#pragma unroll
            for (int q = 0; q < 4; q++) acc[mi][ni][q] = 0.f;

    for (int ch = 0; ch < INC / KCHUNK; ch++) {
        const int k0 = ch * KCHUNK;
        {
            const int r = tid >> 1;
            const int h = (tid & 1) * 32;
            const int n = m0 + r;
            float f[32];
            if (n < NNODES) {
                const float4* p = reinterpret_cast<const float4*>(x + (size_t)n * XROW + k0 + h);
#pragma unroll
                for (int j = 0; j < 8; j++) {
                    float4 v = p[j];
                    f[j * 4 + 0] = v.x; f[j * 4 + 1] = v.y; f[j * 4 + 2] = v.z; f[j * 4 + 3] = v.w;
                }
            } else {
#pragma unroll
                for (int j = 0; j < 32; j++) f[j] = 0.f;
            }
#pragma unroll
            for (int g4 = 0; g4 < 4; g4++) {
                uint4 hi, lo;
                split8(f + g4 * 8, hi, lo);
                const int off = r * SROW + (h + g4 * 8) * 2;
                *reinterpret_cast<uint4*>(sm + SM_AHI + off) = hi;
                *reinterpret_cast<uint4*>(sm + SM_ALO + off) = lo;
            }
        }
        {
            const int r = tid >> 1;
            const int h = (tid & 1) * 32;
            const uint4* ph = reinterpret_cast<const uint4*>(g_whi + (size_t)(nb + r) * INC + k0 + h);
            const uint4* pl = reinterpret_cast<const uint4*>(g_wlo + (size_t)(nb + r) * INC + k0 + h);
            const int off = r * SROW + h * 2;
#pragma unroll
            for (int j = 0; j < 4; j++) {
                *reinterpret_cast<uint4*>(sm + SM_BHI + off + j * 16) = ph[j];
                *reinterpret_cast<uint4*>(sm + SM_BLO + off + j * 16) = pl[j];
            }
        }
        __syncthreads();

#pragma unroll
        for (int ks = 0; ks < 4; ks++) {
            const int kb = ks * 32 + c * 4;
            uint32_t ah[2][4], al[2][4];
#pragma unroll
            for (int mi = 0; mi < 2; mi++) {
                const int base = (mo + mi * 16 + g) * SROW + kb;
                ah[mi][0] = *reinterpret_cast<const uint32_t*>(sm + SM_AHI + base);
                ah[mi][1] = *reinterpret_cast<const uint32_t*>(sm + SM_AHI + base + 8 * SROW);
                ah[mi][2] = *reinterpret_cast<const uint32_t*>(sm + SM_AHI + base + 16);
                ah[mi][3] = *reinterpret_cast<const uint32_t*>(sm + SM_AHI + base + 8 * SROW + 16);
                al[mi][0] = *reinterpret_cast<const uint32_t*>(sm + SM_ALO + base);
                al[mi][1] = *reinterpret_cast<const uint32_t*>(sm + SM_ALO + base + 8 * SROW);
                al[mi][2] = *reinterpret_cast<const uint32_t*>(sm + SM_ALO + base + 16);
                al[mi][3] = *reinterpret_cast<const uint32_t*>(sm + SM_ALO + base + 8 * SROW + 16);
            }
#pragma unroll
            for (int ni = 0; ni < 8; ni++) {
                const int bbase = (no + ni * 8 + g) * SROW + kb;
                uint32_t bh[2], bl[2];
                bh[0] = *reinterpret_cast<const uint32_t*>(sm + SM_BHI + bbase);
                bh[1] = *reinterpret_cast<const uint32_t*>(sm + SM_BHI + bbase + 16);
                bl[0] = *reinterpret_cast<const uint32_t*>(sm + SM_BLO + bbase);
                bl[1] = *reinterpret_cast<const uint32_t*>(sm + SM_BLO + bbase + 16);
                mma16816(acc[0][ni], ah[0], bh);
                mma16816(acc[1][ni], ah[1], bh);
                mma16816(acc[0][ni], ah[0], bl);
                mma16816(acc[1][ni], ah[1], bl);
                mma16816(acc[0][ni], al[0], bh);
                mma16816(acc[1][ni], al[1], bh);
            }
        }
        __syncthreads();
    }

    // ---- epilogue 1: store content as fp16 ----
#pragma unroll
    for (int mi = 0; mi < 2; mi++) {
        const int r0 = m0 + mo + mi * 16 + g;
        const int r1 = r0 + 8;
#pragma unroll
        for (int ni = 0; ni < 8; ni++) {
            const int col = nb + no + ni * 8 + c * 2;
            if (r0 < NNODES) {
                const __half2 h2 = __floats2half2_rn(acc[mi][ni][0], acc[mi][ni][1]);
                *reinterpret_cast<uint32_t*>(
                    reinterpret_cast<char*>(g_contenth) + ((size_t)r0 * HC + col) * 2) =
                    *reinterpret_cast<const uint32_t*>(&h2);
            }
            if (r1 < NNODES) {
                const __half2 h2 = __floats2half2_rn(acc[mi][ni][2], acc[mi][ni][3]);
                *reinterpret_cast<uint32_t*>(
                    reinterpret_cast<char*>(g_contenth) + ((size_t)r1 * HC + col) * 2) =
                    *reinterpret_cast<const uint32_t*>(&h2);
            }
        }
    }

    // ---- epilogue 2: fused attention logits (this warp owns full head h) ----
    const int h = (nb + no) >> 6;          // head index 0..3
    float as[16], ad[16];
#pragma unroll
    for (int ni = 0; ni < 8; ni++) {
#pragma unroll
        for (int q = 0; q < 2; q++) {
            const int ci = ni * 8 + c * 2 + q;
            as[ni * 2 + q] = att[h * 128 + ci];
            ad[ni * 2 + q] = att[h * 128 + 64 + ci];
        }
    }
#pragma unroll
    for (int mi = 0; mi < 2; mi++) {
        float vs0 = 0.f, vd0 = 0.f, vs1 = 0.f, vd1 = 0.f;
#pragma unroll
        for (int ni = 0; ni < 8; ni++) {
            vs0 = fmaf(acc[mi][ni][0], as[ni * 2], fmaf(acc[mi][ni][1], as[ni * 2 + 1], vs0));
            vd0 = fmaf(acc[mi][ni][0], ad[ni * 2], fmaf(acc[mi][ni][1], ad[ni * 2 + 1], vd0));
            vs1 = fmaf(acc[mi][ni][2], as[ni * 2], fmaf(acc[mi][ni][3], as[ni * 2 + 1], vs1));
            vd1 = fmaf(acc[mi][ni][2], ad[ni * 2], fmaf(acc[mi][ni][3], ad[ni * 2 + 1], vd1));
        }
#pragma unroll
        for (int o = 1; o <= 2; o <<= 1) {
            vs0 += __shfl_xor_sync(0xffffffffu, vs0, o);
            vd0 += __shfl_xor_sync(0xffffffffu, vd0, o);
            vs1 += __shfl_xor_sync(0xffffffffu, vs1, o);
            vd1 += __shfl_xor_sync(0xffffffffu, vd1, o);
        }
        if (c == 0) {
            const int r0 = m0 + mo + mi * 16 + g;
            const int r1 = r0 + 8;
            if (r0 < NNODES) {
                red_add_f32(g_s  + r0 * NH + h, vs0);
                red_add_f32(g_dv + r0 * NH + h, vd0);
            }
            if (r1 < NNODES) {
                red_add_f32(g_s  + r1 * NH + h, vs1);
                red_add_f32(g_dv + r1 * NH + h, vd1);
            }
        }
    }
}

// ---------------- K3: fused logits + leakyrelu + exp + denom ----------------
__global__ void __launch_bounds__(256) k_logexp(const int* __restrict__ ei) {
    const int e = blockIdx.x * blockDim.x + threadIdx.x;
    if (e >= ET) return;
    int r, c;
    if (e < E0) { r = ei[e]; c = ei[E0 + e]; } else { r = c = e - E0; }
    const float4 sv = *reinterpret_cast<const float4*>(g_s  + r * NH);
    const float4 dv = *reinterpret_cast<const float4*>(g_dv + c * NH);
    float a0 = sv.x + dv.x, a1 = sv.y + dv.y, a2 = sv.z + dv.z, a3 = sv.w + dv.w;
    a0 = a0 > 0.f ? a0 : 0.2f * a0;
    a1 = a1 > 0.f ? a1 : 0.2f * a1;
    a2 = a2 > 0.f ? a2 : 0.2f * a2;
    a3 = a3 > 0.f ? a3 : 0.2f * a3;
    const float e0 = __expf(a0), e1 = __expf(a1), e2 = __expf(a2), e3 = __expf(a3);
    g_alpha[e] = make_float4(e0, e1, e2, e3);
    red_add_v4(g_denom + r * NH, e0, e1, e2, e3);
}

// ---------------- K4a/b/c: coalesced 3-stage exclusive scan ----------------
__global__ void __launch_bounds__(1024) k_scan1() {
    __shared__ int sp[32];
    const int idx = blockIdx.x * 1024 + threadIdx.x;
    int v = (idx < NNODES) ? g_count[idx] : 0;
#pragma unroll
    for (int o = 16; o > 0; o >>= 1) v += __shfl_xor_sync(0xffffffffu, v, o);
    if ((threadIdx.x & 31) == 0) sp[threadIdx.x >> 5] = v;
    __syncthreads();
    if (threadIdx.x < 32) {
        int s = sp[threadIdx.x];
#pragma unroll
        for (int o = 16; o > 0; o >>= 1) s += __shfl_xor_sync(0xffffffffu, s, o);
        if (threadIdx.x == 0) g_psum[blockIdx.x] = s;
    }
}
__global__ void k_scan2() {
    const int t = threadIdx.x;   // 64 threads
    int v = (t < SCANB) ? g_psum[t] : 0;
    int acc = 0;
#pragma unroll
    for (int o = 1; o < 64; o <<= 1) {
        const int u = __shfl_up_sync(0xffffffffu, v, o, 32);
        if ((t & 31) >= o) v += u;
    }
    __shared__ int w0tot;
    if (t == 31) w0tot = v;
    __syncthreads();
    acc = (t >= 32) ? w0tot : 0;
    if (t < SCANB) g_poff[t] = v + acc - g_psum[t]; // exclusive
    if (t == 0) g_rowptr[NNODES] = ET;
    if (t < 16) g_S[t] = 0.f;
}
__global__ void __launch_bounds__(1024) k_scan3() {
    __shared__ int sw[32];
    const int idx = blockIdx.x * 1024 + threadIdx.x;
    const int lane = threadIdx.x & 31, wid = threadIdx.x >> 5;
    int v = (idx < NNODES) ? g_count[idx] : 0;
    const int mine = v;
#pragma unroll
    for (int o = 1; o < 32; o <<= 1) {
        const int u = __shfl_up_sync(0xffffffffu, v, o);
        if (lane >= o) v += u;
    }
    if (lane == 31) sw[wid] = v;
    __syncthreads();
    if (wid == 0) {
        int s = sw[lane];
#pragma unroll
        for (int o = 1; o < 32; o <<= 1) {
            const int u = __shfl_up_sync(0xffffffffu, s, o);
            if (lane >= o) s += u;
        }
        sw[lane] = s;
    }
    __syncthreads();
    const int warpoff = (wid > 0) ? sw[wid - 1] : 0;
    if (idx < NNODES) {
        const int excl = g_poff[blockIdx.x] + warpoff + v - mine;
        g_rowptr[idx] = excl;
        g_cursor[idx] = excl;
    }
}

// ---------------- K5: scatter edges dest-sorted + normalize + diversity sums ----------------
__global__ void __launch_bounds__(256) k_scatter(const int* __restrict__ ei) {
    __shared__ float red[8][10];
    const int e = blockIdx.x * 256 + threadIdx.x;
    float w0 = 0.f, w1 = 0.f, w2 = 0.f, w3 = 0.f;
    if (e < ET) {
        int r, c;
        if (e < E0) { r = ei[e]; c = ei[E0 + e]; } else { r = c = e - E0; }
        const float4 a   = g_alpha[e];
        const float4 den = *reinterpret_cast<const float4*>(g_denom + r * NH);
        w0 = a.x / (den.x + 1e-16f);
        w1 = a.y / (den.y + 1e-16f);
        w2 = a.z / (den.z + 1e-16f);
        w3 = a.w / (den.w + 1e-16f);
        const int pos = atomicAdd(&g_cursor[r], 1);
        g_scol[pos]   = c;
        g_salpha[pos] = make_float4(w0, w1, w2, w3);
    }
    float p[10];
    p[0] = w0 * w0; p[1] = w0 * w1; p[2] = w0 * w2; p[3] = w0 * w3;
    p[4] = w1 * w1; p[5] = w1 * w2; p[6] = w1 * w3;
    p[7] = w2 * w2; p[8] = w2 * w3; p[9] = w3 * w3;
#pragma unroll
    for (int i = 0; i < 10; i++)
#pragma unroll
        for (int o = 16; o > 0; o >>= 1)
            p[i] += __shfl_xor_sync(0xffffffffu, p[i], o);
    const int wid = threadIdx.x >> 5, lane = threadIdx.x & 31;
    if (lane == 0) {
#pragma unroll
        for (int i = 0; i < 10; i++) red[wid][i] = p[i];
    }
    __syncthreads();
    if (threadIdx.x < 10) {
        float s = 0.f;
#pragma unroll
        for (int k = 0; k < 8; k++) s += red[k][threadIdx.x];
        atomicAdd(&g_S[threadIdx.x], s);
    }
}

// ---------------- K6: CSR aggregation — 2 warps/node, fp16 content, 16-edge batches ----------------
__global__ void __launch_bounds__(256) k_agg(float* __restrict__ out,
                                             const float* __restrict__ bias) {
    const int gw = (blockIdx.x * 256 + threadIdx.x) >> 5;
    const int n = gw >> 1;
    if (n >= NNODES) return;
    const int hf   = gw & 1;
    const int lane = threadIdx.x & 31;
    const int beg = g_rowptr[n];
    const int end = g_rowptr[n + 1];
    const int coff = hf * 32 + lane;         // 4-channel group index
    const float* sal = reinterpret_cast<const float*>(g_salpha);

    float4 acc = make_float4(0.f, 0.f, 0.f, 0.f);
    for (int base = beg; base < end; base += 16) {
        const int slot = lane & 15;
        const int myj = base + slot;
        int   mycol = -1;
        float mywx = 0.f, mywy = 0.f;
        if (myj < end) {
            if (lane < 16) {
                mycol = g_scol[myj];
            } else {
                const float2 w2 = *reinterpret_cast<const float2*>(sal + (size_t)myj * 4 + hf * 2);
                mywx = w2.x; mywy = w2.y;
            }
        }
#pragma unroll
        for (int t = 0; t < 16; t++) {
            const int   c  = __shfl_sync(0xffffffffu, mycol, t);
            const float wx = __shfl_sync(0xffffffffu, mywx, 16 + t);
            const float wy = __shfl_sync(0xffffffffu, mywy, 16 + t);
            if (c >= 0) {
                const float wv = (lane < 16) ? wx : wy;
                const uint2 raw = reinterpret_cast<const uint2*>(
                    reinterpret_cast<const char*>(g_contenth) + (size_t)c * HC * 2)[coff];
                const __half2 h0 = *reinterpret_cast<const __half2*>(&raw.x);
                const __half2 h1 = *reinterpret_cast<const __half2*>(&raw.y);
                const float2 f0 = __half22float2(h0);
                const float2 f1 = __half22float2(h1);
                acc.x = fmaf(wv, f0.x, acc.x);
                acc.y = fmaf(wv, f0.y, acc.y);
                acc.z = fmaf(wv, f1.x, acc.z);
                acc.w = fmaf(wv, f1.y, acc.w);
            }
        }
    }
    const float4 b = reinterpret_cast<const float4*>(bias)[coff];
    reinterpret_cast<float4*>(out + (size_t)n * HC)[coff] =
        make_float4(acc.x + b.x, acc.y + b.y, acc.z + b.z, acc.w + b.w);
}

// ---------------- K7: diversity scalar ----------------
__global__ void k_finish(float* __restrict__ out, int outn) {
    if (blockIdx.x == 0 && threadIdx.x == 0) {
        const float n0 = fmaxf(sqrtf(g_S[0]), 1e-8f);
        const float n1 = fmaxf(sqrtf(g_S[4]), 1e-8f);
        const float n2 = fmaxf(sqrtf(g_S[7]), 1e-8f);
        const float n3 = fmaxf(sqrtf(g_S[9]), 1e-8f);
        float s = 0.f;
        s += 2.f * g_S[1] / (n0 * n1);
        s += 2.f * g_S[2] / (n0 * n2);
        s += 2.f * g_S[3] / (n0 * n3);
        s += 2.f * g_S[5] / (n1 * n2);
        s += 2.f * g_S[6] / (n1 * n3);
        s += 2.f * g_S[8] / (n2 * n3);
        out[outn] = (s / 16.f) * 0.1f;
    }
}

// ---------------- launch ----------------
extern "C" void kernel_launch(void* const* d_in, const int* in_sizes, int n_in,
                              void* d_out, int out_size) {
    const float* x    = (const float*)d_in[0];
    const int*   ei   = (const int*)d_in[1];
    const float* w    = (const float*)d_in[2];
    const float* att  = (const float*)d_in[3];
    const float* patt = (const float*)d_in[4];
    const float* bias = (const float*)d_in[5];
    float* out = (float*)d_out;
    const int outn = out_size - 1;

    static cudaStream_t s2;
    static cudaEvent_t evFork, evJoin;
    static int inited = 0;
    if (!inited) {
        cudaFuncSetAttribute(k_gemm, cudaFuncAttributeMaxDynamicSharedMemorySize, SM_TOT);
        cudaStreamCreateWithFlags(&s2, cudaStreamNonBlocking);
        cudaEventCreateWithFlags(&evFork, cudaEventDisableTiming);
        cudaEventCreateWithFlags(&evJoin, cudaEventDisableTiming);
        inited = 1;
    }

    dim3 ggrid((NNODES + TILE_M - 1) / TILE_M, HC / TILE_N);
    const int posblocks = (NNODES * 32 + 255) / 256;

    // fork: CSR-build chain on side stream (depends only on ei)
    cudaEventRecord(evFork, 0);
    cudaStreamWaitEvent(s2, evFork, 0);
    k_zero_count<<<(NNODES + 255) / 256, 256, 0, s2>>>();
    k_count     <<<(ET + 255) / 256, 256, 0, s2>>>(ei);
    k_scan1     <<<SCANB, 1024, 0, s2>>>();
    k_scan2     <<<1, 64, 0, s2>>>();
    k_scan3     <<<SCANB, 1024, 0, s2>>>();
    cudaEventRecord(evJoin, s2);

    // main chain
    k_init  <<<WSPLITB + posblocks, 256>>>(x, w, patt);
    k_gemm  <<<ggrid, 256, SM_TOT>>>(x, att);
    k_logexp<<<(ET + 255) / 256, 256>>>(ei);

    // join before scatter (needs rowptr/cursor/g_S)
    cudaStreamWaitEvent(0, evJoin, 0);
    k_scatter<<<(ET + 255) / 256, 256>>>(ei);
    k_agg    <<<(NNODES * 2 * 32 + 255) / 256, 256>>>(out, bias);
    k_finish <<<1, 32>>>(out, outn);
}